// round 1
// baseline (speedup 1.0000x reference)
#include <cuda_runtime.h>
#include <cuda_bf16.h>
#include <cstdint>

#define NEGC 1e9f

// Problem constants
#define B_  32
#define T_  512     // T1 == T2
#define D_  256     // D1 == D2
#define O_  256
#define KF_ 8
#define G_  64

// ---------------- scratch (static device arrays, no allocation) ----------------
__device__ float g_R [B_ * O_ * T_];     // R_l [b][o][t]
__device__ float g_Q [B_ * O_ * T_];     // Q_l [b][o][t]
__device__ float g_Uk[KF_ * T_ * O_];    // Uk  [k][t][o]
__device__ float g_Vk[KF_ * T_ * O_];    // Vk  [k][t][o]
__device__ float g_F [B_ * T_ * T_];     // F   [b][i][j]
__device__ float g_WR[B_ * G_ * T_];     // WR  [b][g][t]
__device__ float g_WQ[B_ * G_ * T_];     // WQ  [b][g][s]
__device__ float g_d1[B_ * T_];
__device__ float g_d2[B_ * T_];
__device__ float g_g1[B_ * T_];
__device__ float g_g2[B_ * T_];
__device__ float g_pq[B_ * T_];          // pad_q (1.0 where invalid)
__device__ float g_pv[B_ * T_];          // pad_v

// ---------------- mask decode (dtype-agnostic) ----------------
// Detect the on-disk encoding of the boolean masks from the first bytes of q_mask.
// q_mask[0][0..3] are guaranteed true (len1 >= T/2). Encodings:
//   uint8 bool : bytes 01 01 01 01 ...        -> byte[1] == 1
//   bf16       : bytes 80 3F 80 3F ...        -> byte[1] == 0x3F
//   float32    : bytes 00 00 80 3F ...        -> byte[3] == 0x3F
//   int32      : bytes 01 00 00 00 ...        -> otherwise
__global__ void maskconv_kernel(const unsigned char* __restrict__ q,
                                const unsigned char* __restrict__ v,
                                float* __restrict__ pq, float* __restrict__ pv) {
    int i = blockIdx.x * blockDim.x + threadIdx.x;
    if (i >= B_ * T_) return;
    unsigned char b1 = q[1], b3 = q[3];
    int type = (b1 == 1) ? 0 : (b1 == 0x3F) ? 3 : (b3 == 0x3F) ? 2 : 1;
    bool qv, vv;
    switch (type) {
        case 0: qv = q[i] != 0;                                   vv = v[i] != 0; break;
        case 1: qv = ((const int*)q)[i] != 0;                     vv = ((const int*)v)[i] != 0; break;
        case 2: qv = ((const float*)q)[i] != 0.f;                 vv = ((const float*)v)[i] != 0.f; break;
        default: qv = ((const unsigned short*)q)[i] != 0;         vv = ((const unsigned short*)v)[i] != 0; break;
    }
    pq[i] = qv ? 0.f : 1.f;
    pv[i] = vv ? 0.f : 1.f;
}

// ---------------- Uk/Vk gather: Uk[k][m] = Uflat[m*KF + k] ----------------
__global__ void perm_kernel(const float* __restrict__ U, const float* __restrict__ V,
                            float* __restrict__ Uo, float* __restrict__ Vo) {
    int tid = blockIdx.x * blockDim.x + threadIdx.x;   // 0 .. KF*T*O-1
    if (tid >= KF_ * T_ * O_) return;
    int k = tid >> 17;           // / (T_*O_) = /131072
    int m = tid & (T_ * O_ - 1);
    Uo[tid] = U[m * KF_ + k];
    Vo[tid] = V[m * KF_ + k];
}

// ---------------- generic 64x64 tile GEMM ----------------
// C[b, m, n] = sum_k A[m,k] * Bm[b, k, n]   (A shared across batch)
// EPI: C = relu(C - NEG*pad[b,n] + bias[m])
template <bool EPI>
__global__ void gemm64_kernel(const float* __restrict__ A, const float* __restrict__ Bm,
                              float* __restrict__ C, int K, int N, int Mtot,
                              long strideB, const float* __restrict__ bias,
                              const float* __restrict__ pad) {
    int b  = blockIdx.z;
    int n0 = blockIdx.x * 64;
    int m0 = blockIdx.y * 64;
    const float* Bb = Bm + (long)b * strideB;

    __shared__ float As[16][68];   // [kk][m]
    __shared__ float Bs[16][68];   // [kk][n]

    int tid = threadIdx.x;
    int tx = tid & 15, ty = tid >> 4;
    float acc[4][4] = {};

    for (int k0 = 0; k0 < K; k0 += 16) {
        #pragma unroll
        for (int p = 0; p < 4; p++) {
            int r = (tid >> 4) + p * 16;     // 0..63 (m)
            int c = tid & 15;                // 0..15 (kk)
            As[c][r] = A[(m0 + r) * K + k0 + c];
        }
        #pragma unroll
        for (int p = 0; p < 4; p++) {
            int r = (tid >> 6) + p * 4;      // 0..15 (kk)
            int c = tid & 63;                // 0..63 (n)
            Bs[r][c] = Bb[(long)(k0 + r) * N + n0 + c];
        }
        __syncthreads();
        #pragma unroll
        for (int kk = 0; kk < 16; kk++) {
            float a[4];
            #pragma unroll
            for (int i = 0; i < 4; i++) a[i] = As[kk][ty * 4 + i];
            float4 bb = *reinterpret_cast<const float4*>(&Bs[kk][tx * 4]);
            float bv[4] = {bb.x, bb.y, bb.z, bb.w};
            #pragma unroll
            for (int i = 0; i < 4; i++)
                #pragma unroll
                for (int j = 0; j < 4; j++)
                    acc[i][j] += a[i] * bv[j];
        }
        __syncthreads();
    }

    #pragma unroll
    for (int i = 0; i < 4; i++) {
        int m = m0 + ty * 4 + i;
        #pragma unroll
        for (int j = 0; j < 4; j++) {
            int n = n0 + tx * 4 + j;
            float vv = acc[i][j];
            if (EPI) {
                vv -= NEGC * pad[b * N + n];
                vv += bias[m];
                vv = fmaxf(vv, 0.f);
            }
            C[(long)b * Mtot * N + (long)m * N + n] = vv;
        }
    }
}

// ---------------- F kernel (fused factorized bilinear) ----------------
// F[b,i,j] = sum_k (sum_o Uk[k,i,o]*R[b,o,j]) * (sum_o Vk[k,i,o]*Q[b,o,j])
__global__ void f_kernel(const float* __restrict__ Uk, const float* __restrict__ Vk,
                         const float* __restrict__ R, const float* __restrict__ Q,
                         float* __restrict__ F) {
    int b  = blockIdx.z;
    int j0 = blockIdx.x * 64;
    int i0 = blockIdx.y * 64;

    __shared__ float Us[16][68], Vs[16][68];   // [oo][i]
    __shared__ float Rs[16][68], Qs[16][68];   // [oo][j]

    int tid = threadIdx.x;
    int tx = tid & 15, ty = tid >> 4;
    float f[4][4] = {};

    const float* Rb = R + (long)b * O_ * T_;
    const float* Qb = Q + (long)b * O_ * T_;

    for (int k = 0; k < KF_; k++) {
        float a1[4][4] = {}, a2[4][4] = {};
        const float* Ukk = Uk + (long)k * T_ * O_;
        const float* Vkk = Vk + (long)k * T_ * O_;

        for (int o0 = 0; o0 < O_; o0 += 16) {
            #pragma unroll
            for (int p = 0; p < 4; p++) {
                int r = (tid >> 4) + p * 16;    // i 0..63
                int c = tid & 15;               // oo 0..15
                Us[c][r] = Ukk[(i0 + r) * O_ + o0 + c];
                Vs[c][r] = Vkk[(i0 + r) * O_ + o0 + c];
            }
            #pragma unroll
            for (int p = 0; p < 4; p++) {
                int r = (tid >> 6) + p * 4;     // oo 0..15
                int c = tid & 63;               // j 0..63
                Rs[r][c] = Rb[(o0 + r) * T_ + j0 + c];
                Qs[r][c] = Qb[(o0 + r) * T_ + j0 + c];
            }
            __syncthreads();
            #pragma unroll
            for (int oo = 0; oo < 16; oo++) {
                float u[4], vv[4];
                #pragma unroll
                for (int i = 0; i < 4; i++) { u[i] = Us[oo][ty * 4 + i]; vv[i] = Vs[oo][ty * 4 + i]; }
                float4 r4 = *reinterpret_cast<const float4*>(&Rs[oo][tx * 4]);
                float4 q4 = *reinterpret_cast<const float4*>(&Qs[oo][tx * 4]);
                float rr[4] = {r4.x, r4.y, r4.z, r4.w};
                float qq[4] = {q4.x, q4.y, q4.z, q4.w};
                #pragma unroll
                for (int i = 0; i < 4; i++)
                    #pragma unroll
                    for (int j = 0; j < 4; j++) {
                        a1[i][j] += u[i]  * rr[j];
                        a2[i][j] += vv[i] * qq[j];
                    }
            }
            __syncthreads();
        }
        #pragma unroll
        for (int i = 0; i < 4; i++)
            #pragma unroll
            for (int j = 0; j < 4; j++)
                f[i][j] += a1[i][j] * a2[i][j];
    }

    #pragma unroll
    for (int i = 0; i < 4; i++)
        #pragma unroll
        for (int j = 0; j < 4; j++)
            F[(long)b * T_ * T_ + (long)(i0 + ty * 4 + i) * T_ + j0 + tx * 4 + j] = f[i][j];
}

// ---------------- fused M + d kernel ----------------
// d[b,col] = sum_g w[g] * relu( Bias[b,g,col] + sum_i Mul[b,g,i]*F[b,i,col] ) - NEG*pad[b,col]
__global__ void md_kernel(const float* __restrict__ Bias, const float* __restrict__ Mul,
                          const float* __restrict__ F, const float* __restrict__ w,
                          const float* __restrict__ pad, float* __restrict__ d) {
    int b  = blockIdx.y;
    int c0 = blockIdx.x * 64;

    __shared__ float Ms[16][68];   // [ii][g]
    __shared__ float Fs[16][68];   // [ii][col]
    __shared__ float red[16][64];

    int tid = threadIdx.x;
    int tx = tid & 15, ty = tid >> 4;
    float acc[4][4] = {};

    const float* Mb = Mul + (long)b * G_ * T_;
    const float* Fb = F   + (long)b * T_ * T_;

    for (int i0 = 0; i0 < T_; i0 += 16) {
        #pragma unroll
        for (int p = 0; p < 4; p++) {
            int r = (tid >> 4) + p * 16;   // g 0..63
            int c = tid & 15;              // ii 0..15
            Ms[c][r] = Mb[r * T_ + i0 + c];
        }
        #pragma unroll
        for (int p = 0; p < 4; p++) {
            int r = (tid >> 6) + p * 4;    // ii
            int c = tid & 63;              // col
            Fs[r][c] = Fb[(long)(i0 + r) * T_ + c0 + c];
        }
        __syncthreads();
        #pragma unroll
        for (int ii = 0; ii < 16; ii++) {
            float m[4];
            #pragma unroll
            for (int i = 0; i < 4; i++) m[i] = Ms[ii][ty * 4 + i];
            float4 f4 = *reinterpret_cast<const float4*>(&Fs[ii][tx * 4]);
            float ff[4] = {f4.x, f4.y, f4.z, f4.w};
            #pragma unroll
            for (int i = 0; i < 4; i++)
                #pragma unroll
                for (int j = 0; j < 4; j++)
                    acc[i][j] += m[i] * ff[j];
        }
        __syncthreads();
    }

    float part[4] = {0.f, 0.f, 0.f, 0.f};
    #pragma unroll
    for (int gq = 0; gq < 4; gq++) {
        int g = ty * 4 + gq;
        float wg = w[g];
        #pragma unroll
        for (int c = 0; c < 4; c++) {
            float vv = acc[gq][c] + Bias[(long)b * G_ * T_ + g * T_ + c0 + tx * 4 + c];
            part[c] += wg * fmaxf(vv, 0.f);
        }
    }
    #pragma unroll
    for (int c = 0; c < 4; c++) red[ty][tx * 4 + c] = part[c];
    __syncthreads();
    #pragma unroll
    for (int s = 8; s > 0; s >>= 1) {
        if (ty < s) {
            #pragma unroll
            for (int c = 0; c < 4; c++) red[ty][tx * 4 + c] += red[ty + s][tx * 4 + c];
        }
        __syncthreads();
    }
    if (ty == 0) {
        #pragma unroll
        for (int c = 0; c < 4; c++) {
            int col = c0 + tx * 4 + c;
            d[b * T_ + col] = red[0][tx * 4 + c] - NEGC * pad[b * T_ + col];
        }
    }
}

// ---------------- softmax ----------------
__global__ void softmax_kernel(const float* __restrict__ d1, const float* __restrict__ d2,
                               float* __restrict__ g1, float* __restrict__ g2) {
    int b = blockIdx.x;
    const float* d = blockIdx.y ? d2 : d1;
    float* g = blockIdx.y ? g2 : g1;
    int t = threadIdx.x;   // 512 threads

    float v = d[b * T_ + t];
    __shared__ float red[16];
    float m = v;
    #pragma unroll
    for (int o = 16; o; o >>= 1) m = fmaxf(m, __shfl_xor_sync(0xffffffffu, m, o));
    if ((t & 31) == 0) red[t >> 5] = m;
    __syncthreads();
    if (t < 32) {
        float x = (t < 16) ? red[t] : -3.4e38f;
        #pragma unroll
        for (int o = 8; o; o >>= 1) x = fmaxf(x, __shfl_xor_sync(0xffffffffu, x, o));
        if (t == 0) red[0] = x;
    }
    __syncthreads();
    float mx = red[0];
    __syncthreads();

    float e = expf(v - mx);
    float s = e;
    #pragma unroll
    for (int o = 16; o; o >>= 1) s += __shfl_xor_sync(0xffffffffu, s, o);
    if ((t & 31) == 0) red[t >> 5] = s;
    __syncthreads();
    if (t < 32) {
        float x = (t < 16) ? red[t] : 0.f;
        #pragma unroll
        for (int o = 8; o; o >>= 1) x += __shfl_xor_sync(0xffffffffu, x, o);
        if (t == 0) red[0] = x;
    }
    __syncthreads();
    g[b * T_ + t] = e / red[0];
}

// ---------------- final reduction ----------------
// trace[b,o] = sum_t gv[b,t]*Rflat[b, t*O + o]; out = trace * log
__global__ void final_kernel(const float* __restrict__ R, const float* __restrict__ Q,
                             const float* __restrict__ gv, const float* __restrict__ gq,
                             float* __restrict__ out) {
    int b = blockIdx.x;
    __shared__ float sgv[T_], sgq[T_];
    int tid = threadIdx.x;   // 512
    sgv[tid] = gv[b * T_ + tid];
    sgq[tid] = gq[b * T_ + tid];
    __syncthreads();

    int o = tid & 255;
    int h = tid >> 8;
    const float* Rb = R + (long)b * O_ * T_;
    const float* Qb = Q + (long)b * O_ * T_;
    float tr = 0.f, lg = 0.f;
    #pragma unroll 4
    for (int t = h * 256; t < h * 256 + 256; t++) {
        tr += sgv[t] * Rb[t * O_ + o];
        lg += sgq[t] * Qb[t * O_ + o];
    }
    __shared__ float str[2][256], slg[2][256];
    str[h][o] = tr;
    slg[h][o] = lg;
    __syncthreads();
    if (h == 0) out[b * O_ + o] = (str[0][o] + str[1][o]) * (slg[0][o] + slg[1][o]);
}

// ---------------- launcher ----------------
extern "C" void kernel_launch(void* const* d_in, const int* in_sizes, int n_in,
                              void* d_out, int out_size) {
    const float* x0  = (const float*)d_in[0];
    const float* x1  = (const float*)d_in[1];
    const unsigned char* qm = (const unsigned char*)d_in[2];
    const unsigned char* vm = (const unsigned char*)d_in[3];
    const float* W_R = (const float*)d_in[4];
    const float* W_Q = (const float*)d_in[5];
    const float* br  = (const float*)d_in[6];
    const float* bq  = (const float*)d_in[7];
    const float* U   = (const float*)d_in[8];
    const float* V   = (const float*)d_in[9];
    const float* W2R = (const float*)d_in[10];
    const float* W2Q = (const float*)d_in[11];
    const float* wmv = (const float*)d_in[12];
    const float* wmq = (const float*)d_in[13];
    float* out = (float*)d_out;

    float *pR, *pQ, *pUk, *pVk, *pF, *pWR, *pWQ, *pd1, *pd2, *pg1, *pg2, *ppq, *ppv;
    cudaGetSymbolAddress((void**)&pR,  g_R);
    cudaGetSymbolAddress((void**)&pQ,  g_Q);
    cudaGetSymbolAddress((void**)&pUk, g_Uk);
    cudaGetSymbolAddress((void**)&pVk, g_Vk);
    cudaGetSymbolAddress((void**)&pF,  g_F);
    cudaGetSymbolAddress((void**)&pWR, g_WR);
    cudaGetSymbolAddress((void**)&pWQ, g_WQ);
    cudaGetSymbolAddress((void**)&pd1, g_d1);
    cudaGetSymbolAddress((void**)&pd2, g_d2);
    cudaGetSymbolAddress((void**)&pg1, g_g1);
    cudaGetSymbolAddress((void**)&pg2, g_g2);
    cudaGetSymbolAddress((void**)&ppq, g_pq);
    cudaGetSymbolAddress((void**)&ppv, g_pv);

    // 1. mask decode + Uk/Vk gather (independent)
    maskconv_kernel<<<(B_ * T_ + 255) / 256, 256>>>(qm, vm, ppq, ppv);
    perm_kernel<<<(KF_ * T_ * O_ + 255) / 256, 256>>>(U, V, pUk, pVk);

    // 2. R_l, Q_l GEMMs with mask/bias/relu epilogue
    gemm64_kernel<true><<<dim3(T_ / 64, O_ / 64, B_), 256>>>(
        W_R, x0, pR, D_, T_, O_, (long)D_ * T_, br, ppq);
    gemm64_kernel<true><<<dim3(T_ / 64, O_ / 64, B_), 256>>>(
        W_Q, x1, pQ, D_, T_, O_, (long)D_ * T_, bq, ppv);

    // 3. fused factorized bilinear F
    f_kernel<<<dim3(T_ / 64, T_ / 64, B_), 256>>>(pUk, pVk, pR, pQ, pF);

    // 4. WR = W2_R @ R_l ; WQ = W2_Q @ Q_l
    gemm64_kernel<false><<<dim3(T_ / 64, 1, B_), 256>>>(
        W2R, pR, pWR, O_, T_, G_, (long)O_ * T_, nullptr, nullptr);
    gemm64_kernel<false><<<dim3(T_ / 64, 1, B_), 256>>>(
        W2Q, pQ, pWQ, O_, T_, G_, (long)O_ * T_, nullptr, nullptr);

    // 5. fused M_v/M_q + relu + g-reduction -> d1, d2
    md_kernel<<<dim3(T_ / 64, B_), 256>>>(pWR, pWQ, pF, wmv, ppq, pd1);
    md_kernel<<<dim3(T_ / 64, B_), 256>>>(pWQ, pWR, pF, wmq, ppv, pd2);

    // 6. softmax -> gamma_v, gamma_q
    softmax_kernel<<<dim3(B_, 2), T_>>>(pd1, pd2, pg1, pg2);

    // 7. final weighted reductions + elementwise product
    final_kernel<<<B_, T_>>>(pR, pQ, pg1, pg2, out);
}